// round 12
// baseline (speedup 1.0000x reference)
#include <cuda_runtime.h>
#include <cstdint>

// Per-pixel 3x3 conv, kernels shared across channels, edge-replication pad.
// img [1,3,1024,1024] f32, K [9,1024,1024] f32, out [1,3,1024,1024] f32.
//
// R12 = R9's traffic-minimal structure (RPT=4 register row-rolling, shuffle
// halos, 128-thr CTAs, grid 512) with the K-tap stream moved to cp.async
// (LDGSTS) -> shared memory, double-buffered. Thread-private smem slots mean
// no __syncthreads: cp.async.wait_group alone orders producer/consumer.
// This guarantees the next row's 9 K loads are in flight during this row's
// FMAs regardless of ptxas register heuristics (R9's reg-resident double
// buffer was silently serialized: regs=90 < the 108+ needed to hold it).

#define H 1024
#define W 1024
#define HW (H * W)
#define RPT 4              // output rows per thread

__global__ __launch_bounds__(128)
void reblur_kernel(const float* __restrict__ img,
                   const float* __restrict__ ker,
                   float* __restrict__ out)
{
    // [stage][tap][thread] : thread-private 16B slots, conflict-free LDS.128.
    __shared__ float4 ksm[2][9][128];

    const int bid  = blockIdx.x;           // 512 blocks
    const int tid  = threadIdx.x;          // 128 threads -> 512 px of one row
    const int lane = tid & 31;

    const int w0 = (bid & 1) * 512 + tid * 4;   // 4-px column start
    const int h0 = (bid >> 1) * RPT;            // first output row

    const int  wl  = (w0 > 0)     ? w0 - 1 : 0;      // clamped left halo col
    const int  wr  = (w0 + 4 < W) ? w0 + 4 : W - 1;  // clamped right halo col
    const bool isL = (lane == 0);
    const bool isR = (lane == 31);

    // cp.async one output row's 9 K taps into stage s (16B per tap per thread).
    auto issue_k = [&](int row, int s) {
        const float* kp = ker + row * W + w0;
        const uint32_t sbase =
            (uint32_t)__cvta_generic_to_shared(&ksm[s][0][tid]);
        #pragma unroll
        for (int t = 0; t < 9; t++) {
            const uint64_t g = __cvta_generic_to_global(kp + t * HW);
            asm volatile(
                "cp.async.cg.shared.global [%0], [%1], 16;\n"
                :: "r"(sbase + (uint32_t)(t * 128 * 16)), "l"(g) : "memory");
        }
    };

    // ---- prologue: rows h0, h0+1 K taps in flight; image window init -------
    issue_k(h0, 0);
    asm volatile("cp.async.commit_group;\n" ::: "memory");
    issue_k(h0 + 1, 1);
    asm volatile("cp.async.commit_group;\n" ::: "memory");

    float4 m[3][3];            // image window [channel][row: h-1,h,h+1]
    int rowi[3];
    #pragma unroll
    for (int j = 0; j < 3; j++) {
        int row = h0 - 1 + j;
        rowi[j] = (row < 0) ? 0 : row;
        #pragma unroll
        for (int c = 0; c < 3; c++)
            m[c][j] = *reinterpret_cast<const float4*>(img + c * HW + rowi[j] * W + w0);
    }

    #pragma unroll
    for (int r = 0; r < RPT; r++) {
        const int h   = h0 + r;
        const int cur = r & 1;

        // Prefetch next image window row (LDG in flight during compute).
        float4 mn[3];
        int nrow = h + 2;
        nrow = (nrow > H - 1) ? H - 1 : nrow;
        if (r < RPT - 1) {
            #pragma unroll
            for (int c = 0; c < 3; c++)
                mn[c] = *reinterpret_cast<const float4*>(img + c * HW + nrow * W + w0);
        }

        // Current row's K stage complete (<=1 younger group still in flight).
        asm volatile("cp.async.wait_group 1;\n" ::: "memory");

        float acc[3][4];
        #pragma unroll
        for (int c = 0; c < 3; c++)
            #pragma unroll
            for (int x = 0; x < 4; x++)
                acc[c][x] = 0.f;

        #pragma unroll
        for (int j = 0; j < 3; j++) {
            const float4 k0 = ksm[cur][j * 3 + 0][tid];
            const float4 k1 = ksm[cur][j * 3 + 1][tid];
            const float4 k2 = ksm[cur][j * 3 + 2][tid];

            #pragma unroll
            for (int c = 0; c < 3; c++) {
                const float sl = __shfl_up_sync  (0xffffffffu, m[c][j].w, 1);
                const float sr = __shfl_down_sync(0xffffffffu, m[c][j].x, 1);
                // Boundary lanes: predicated 1-wavefront scalar loads; index
                // clamping also realizes the image-edge replication.
                const float v0 = isL ? img[c * HW + rowi[j] * W + wl] : sl;
                const float v5 = isR ? img[c * HW + rowi[j] * W + wr] : sr;
                const float v1 = m[c][j].x;
                const float v2 = m[c][j].y;
                const float v3 = m[c][j].z;
                const float v4 = m[c][j].w;

                acc[c][0] = fmaf(v0, k0.x, acc[c][0]);
                acc[c][1] = fmaf(v1, k0.y, acc[c][1]);
                acc[c][2] = fmaf(v2, k0.z, acc[c][2]);
                acc[c][3] = fmaf(v3, k0.w, acc[c][3]);

                acc[c][0] = fmaf(v1, k1.x, acc[c][0]);
                acc[c][1] = fmaf(v2, k1.y, acc[c][1]);
                acc[c][2] = fmaf(v3, k1.z, acc[c][2]);
                acc[c][3] = fmaf(v4, k1.w, acc[c][3]);

                acc[c][0] = fmaf(v2, k2.x, acc[c][0]);
                acc[c][1] = fmaf(v3, k2.y, acc[c][1]);
                acc[c][2] = fmaf(v4, k2.z, acc[c][2]);
                acc[c][3] = fmaf(v5, k2.w, acc[c][3]);
            }
        }

        #pragma unroll
        for (int c = 0; c < 3; c++) {
            float4 o;
            o.x = acc[c][0]; o.y = acc[c][1]; o.z = acc[c][2]; o.w = acc[c][3];
            *reinterpret_cast<float4*>(out + c * HW + h * W + w0) = o;
        }

        // Refill the stage we just consumed with row r+2's K taps (if any);
        // commit every iteration (empty groups keep the wait count aligned).
        if (r + 2 < RPT)
            issue_k(h0 + r + 2, cur);
        asm volatile("cp.async.commit_group;\n" ::: "memory");

        // Roll image window with the prefetched row.
        if (r < RPT - 1) {
            rowi[0] = rowi[1]; rowi[1] = rowi[2]; rowi[2] = nrow;
            #pragma unroll
            for (int c = 0; c < 3; c++) {
                m[c][0] = m[c][1];
                m[c][1] = m[c][2];
                m[c][2] = mn[c];
            }
        }
    }
}

extern "C" void kernel_launch(void* const* d_in, const int* in_sizes, int n_in,
                              void* d_out, int out_size)
{
    const float* img = (const float*)d_in[0];   // [1,3,1024,1024]
    const float* ker = (const float*)d_in[1];   // [9,1024,1024]
    float* out = (float*)d_out;                 // [1,3,1024,1024]

    // 2 width-halves x 256 row-groups = 512 CTAs of 128 threads.
    reblur_kernel<<<512, 128>>>(img, ker, out);
}

// round 13
// speedup vs baseline: 1.1805x; 1.1805x over previous
#include <cuda_runtime.h>

// Per-pixel 3x3 conv, kernels shared across channels, edge-replication pad.
// img [1,3,1024,1024] f32, K [9,1024,1024] f32, out [1,3,1024,1024] f32.
//
// R13 = R9's kernel (RPT row-rolling, double-buffered K prefetch, shuffle
// halos, 128-thr CTAs) with WAVE-BALANCED partitioning. All variants plateau
// at ~6.6-7.0 TB/s effective (LTS cap), so wall = max per-SM bytes. R9's 512
// CTAs = 3.46/SM -> 1.156x tail. Here: 592 CTAs = exactly 4/SM; 272 CTAs do
// 4 rows, 320 do 3 rows; 4-row CTAs at bid<272 so each SM (bid%148 residue
// class) gets 13-14 row-units vs avg 13.84 -> 1.012x tail.

#define H 1024
#define W 1024
#define HW (H * W)

template<int NR>
__device__ __forceinline__
void process_rows(const float* __restrict__ img,
                  const float* __restrict__ ker,
                  float* __restrict__ out,
                  int h0, int w0, int lane)
{
    const int  wl  = (w0 > 0)     ? w0 - 1 : 0;
    const int  wr  = (w0 + 4 < W) ? w0 + 4 : W - 1;
    const bool isL = (lane == 0);
    const bool isR = (lane == 31);

    float4 m [3][3];           // image window [channel][row: h-1,h,h+1]
    float  lv[3][3], rv[3][3]; // rolled boundary halos (lanes 0/31)
    float4 kbuf[2][9];         // double-buffered per-pixel K taps

    #pragma unroll
    for (int j = 0; j < 3; j++) {
        int row = h0 - 1 + j;
        row = (row < 0) ? 0 : row;
        #pragma unroll
        for (int c = 0; c < 3; c++) {
            const float* p = img + c * HW + row * W;
            m[c][j]  = *reinterpret_cast<const float4*>(p + w0);
            lv[c][j] = isL ? p[wl] : 0.f;
            rv[c][j] = isR ? p[wr] : 0.f;
        }
    }
    {
        const float* kp = ker + h0 * W + w0;
        #pragma unroll
        for (int t = 0; t < 9; t++)
            kbuf[0][t] = *reinterpret_cast<const float4*>(kp + t * HW);
    }

    #pragma unroll
    for (int r = 0; r < NR; r++) {
        const int h   = h0 + r;
        const int cur = r & 1;

        // Prefetch next row's K taps + next window row before computing.
        if (r < NR - 1) {
            const float* kp = ker + (h + 1) * W + w0;
            #pragma unroll
            for (int t = 0; t < 9; t++)
                kbuf[cur ^ 1][t] = *reinterpret_cast<const float4*>(kp + t * HW);
        }
        float4 mn[3]; float lvn[3], rvn[3];
        if (r < NR - 1) {
            int nrow = h + 2;
            nrow = (nrow > H - 1) ? H - 1 : nrow;
            #pragma unroll
            for (int c = 0; c < 3; c++) {
                const float* p = img + c * HW + nrow * W;
                mn[c]  = *reinterpret_cast<const float4*>(p + w0);
                lvn[c] = isL ? p[wl] : 0.f;
                rvn[c] = isR ? p[wr] : 0.f;
            }
        }

        #pragma unroll
        for (int c = 0; c < 3; c++) {
            float acc0 = 0.f, acc1 = 0.f, acc2 = 0.f, acc3 = 0.f;
            #pragma unroll
            for (int j = 0; j < 3; j++) {
                const float sl = __shfl_up_sync  (0xffffffffu, m[c][j].w, 1);
                const float sr = __shfl_down_sync(0xffffffffu, m[c][j].x, 1);
                const float v0 = isL ? lv[c][j] : sl;
                const float v5 = isR ? rv[c][j] : sr;
                const float v1 = m[c][j].x;
                const float v2 = m[c][j].y;
                const float v3 = m[c][j].z;
                const float v4 = m[c][j].w;

                float4 kv;
                kv = kbuf[cur][j * 3 + 0];
                acc0 = fmaf(v0, kv.x, acc0);
                acc1 = fmaf(v1, kv.y, acc1);
                acc2 = fmaf(v2, kv.z, acc2);
                acc3 = fmaf(v3, kv.w, acc3);
                kv = kbuf[cur][j * 3 + 1];
                acc0 = fmaf(v1, kv.x, acc0);
                acc1 = fmaf(v2, kv.y, acc1);
                acc2 = fmaf(v3, kv.z, acc2);
                acc3 = fmaf(v4, kv.w, acc3);
                kv = kbuf[cur][j * 3 + 2];
                acc0 = fmaf(v2, kv.x, acc0);
                acc1 = fmaf(v3, kv.y, acc1);
                acc2 = fmaf(v4, kv.z, acc2);
                acc3 = fmaf(v5, kv.w, acc3);
            }
            float4 o; o.x = acc0; o.y = acc1; o.z = acc2; o.w = acc3;
            *reinterpret_cast<float4*>(out + c * HW + h * W + w0) = o;
        }

        if (r < NR - 1) {
            #pragma unroll
            for (int c = 0; c < 3; c++) {
                m[c][0]  = m[c][1];  m[c][1]  = m[c][2];  m[c][2]  = mn[c];
                lv[c][0] = lv[c][1]; lv[c][1] = lv[c][2]; lv[c][2] = lvn[c];
                rv[c][0] = rv[c][1]; rv[c][1] = rv[c][2]; rv[c][2] = rvn[c];
            }
        }
    }
}

__global__ __launch_bounds__(128)
void reblur_kernel(const float* __restrict__ img,
                   const float* __restrict__ ker,
                   float* __restrict__ out)
{
    const int bid  = blockIdx.x;            // 592 blocks
    const int tid  = threadIdx.x;           // 128 threads -> 512 px of one row
    const int lane = tid & 31;

    // Partition (per width-half): 136 groups of 4 rows (rows 0..543), then
    // 160 groups of 3 rows (rows 544..1023). 4-row CTAs live at bid<272 so
    // each bid%148 residue class sums to 13-14 row-units (near-perfect wave).
    if (bid < 272) {
        const int i4   = bid;
        const int half = i4 & 1;
        const int g    = i4 >> 1;                 // 0..135
        const int w0   = half * 512 + tid * 4;
        process_rows<4>(img, ker, out, 4 * g, w0, lane);
    } else {
        const int i3   = bid - 272;
        const int half = i3 & 1;
        const int g    = i3 >> 1;                 // 0..159
        const int w0   = half * 512 + tid * 4;
        process_rows<3>(img, ker, out, 544 + 3 * g, w0, lane);
    }
}

extern "C" void kernel_launch(void* const* d_in, const int* in_sizes, int n_in,
                              void* d_out, int out_size)
{
    const float* img = (const float*)d_in[0];   // [1,3,1024,1024]
    const float* ker = (const float*)d_in[1];   // [9,1024,1024]
    float* out = (float*)d_out;                 // [1,3,1024,1024]

    // 592 CTAs = exactly 4 per SM (148 SMs), mixed 4-row/3-row for balance.
    reblur_kernel<<<592, 128>>>(img, ker, out);
}

// round 14
// speedup vs baseline: 1.3772x; 1.1667x over previous
#include <cuda_runtime.h>

// Per-pixel 3x3 conv, kernels shared across channels, edge-replication pad.
// img [1,3,1024,1024] f32, K [9,1024,1024] f32, out [1,3,1024,1024] f32.
//
// R14 = R9 exactly (RPT=4 register row-rolling, double-buffered K prefetch,
// shuffle halos, 512x128) + __ldcs (evict-first) on the K-tap stream ONLY.
// K is read-once dead data; default policy lets its 36MB/launch stream evict
// the img/out lines from L2 between graph replays, forcing ~60MB DRAM per
// launch. Evict-first K keeps img+out L2-resident across replays -> steady-
// state DRAM drops toward 36MB/launch.

#define H 1024
#define W 1024
#define HW (H * W)
#define RPT 4              // output rows per thread

__global__ __launch_bounds__(128)
void reblur_kernel(const float* __restrict__ img,
                   const float* __restrict__ ker,
                   float* __restrict__ out)
{
    const int bid  = blockIdx.x;           // 512 blocks
    const int tid  = threadIdx.x;          // 128 threads -> 512 px of one row
    const int lane = tid & 31;

    const int w0 = (bid & 1) * 512 + tid * 4;   // 4-px column start
    const int h0 = (bid >> 1) * RPT;            // first output row

    const int  wl  = (w0 > 0)     ? w0 - 1 : 0;      // clamped left halo col
    const int  wr  = (w0 + 4 < W) ? w0 + 4 : W - 1;  // clamped right halo col
    const bool isL = (lane == 0);
    const bool isR = (lane == 31);

    float4 m [3][3];           // image window [channel][row: h-1,h,h+1]
    float  lv[3][3], rv[3][3]; // rolled boundary halos (lanes 0/31)
    float4 kbuf[2][9];         // double-buffered per-pixel K taps

    // ---- init: window rows h0-1,h0,h0+1 and row h0's K taps, all in flight --
    #pragma unroll
    for (int j = 0; j < 3; j++) {
        int row = h0 - 1 + j;
        row = (row < 0) ? 0 : row;
        #pragma unroll
        for (int c = 0; c < 3; c++) {
            const float* p = img + c * HW + row * W;
            m[c][j]  = *reinterpret_cast<const float4*>(p + w0);
            lv[c][j] = isL ? p[wl] : 0.f;
            rv[c][j] = isR ? p[wr] : 0.f;
        }
    }
    {
        const float4* kp = reinterpret_cast<const float4*>(ker + h0 * W + w0);
        #pragma unroll
        for (int t = 0; t < 9; t++)
            kbuf[0][t] = __ldcs(kp + t * (HW / 4));
    }

    #pragma unroll
    for (int r = 0; r < RPT; r++) {
        const int h   = h0 + r;
        const int cur = r & 1;

        // ---- prefetch phase: next row's K taps + next window row ----------
        if (r < RPT - 1) {
            const float4* kp =
                reinterpret_cast<const float4*>(ker + (h + 1) * W + w0);
            #pragma unroll
            for (int t = 0; t < 9; t++)
                kbuf[cur ^ 1][t] = __ldcs(kp + t * (HW / 4));
        }
        float4 mn[3]; float lvn[3], rvn[3];
        if (r < RPT - 1) {
            int nrow = h + 2;
            nrow = (nrow > H - 1) ? H - 1 : nrow;
            #pragma unroll
            for (int c = 0; c < 3; c++) {
                const float* p = img + c * HW + nrow * W;
                mn[c]  = *reinterpret_cast<const float4*>(p + w0);
                lvn[c] = isL ? p[wl] : 0.f;
                rvn[c] = isR ? p[wr] : 0.f;
            }
        }

        // ---- compute row h with current K buffer --------------------------
        #pragma unroll
        for (int c = 0; c < 3; c++) {
            float acc0 = 0.f, acc1 = 0.f, acc2 = 0.f, acc3 = 0.f;
            #pragma unroll
            for (int j = 0; j < 3; j++) {
                const float sl = __shfl_up_sync  (0xffffffffu, m[c][j].w, 1);
                const float sr = __shfl_down_sync(0xffffffffu, m[c][j].x, 1);
                const float v0 = isL ? lv[c][j] : sl;
                const float v5 = isR ? rv[c][j] : sr;
                const float v1 = m[c][j].x;
                const float v2 = m[c][j].y;
                const float v3 = m[c][j].z;
                const float v4 = m[c][j].w;

                float4 kv;
                kv = kbuf[cur][j * 3 + 0];
                acc0 = fmaf(v0, kv.x, acc0);
                acc1 = fmaf(v1, kv.y, acc1);
                acc2 = fmaf(v2, kv.z, acc2);
                acc3 = fmaf(v3, kv.w, acc3);
                kv = kbuf[cur][j * 3 + 1];
                acc0 = fmaf(v1, kv.x, acc0);
                acc1 = fmaf(v2, kv.y, acc1);
                acc2 = fmaf(v3, kv.z, acc2);
                acc3 = fmaf(v4, kv.w, acc3);
                kv = kbuf[cur][j * 3 + 2];
                acc0 = fmaf(v2, kv.x, acc0);
                acc1 = fmaf(v3, kv.y, acc1);
                acc2 = fmaf(v4, kv.z, acc2);
                acc3 = fmaf(v5, kv.w, acc3);
            }
            float4 o; o.x = acc0; o.y = acc1; o.z = acc2; o.w = acc3;
            *reinterpret_cast<float4*>(out + c * HW + h * W + w0) = o;
        }

        // ---- roll window with prefetched row ------------------------------
        if (r < RPT - 1) {
            #pragma unroll
            for (int c = 0; c < 3; c++) {
                m[c][0]  = m[c][1];  m[c][1]  = m[c][2];  m[c][2]  = mn[c];
                lv[c][0] = lv[c][1]; lv[c][1] = lv[c][2]; lv[c][2] = lvn[c];
                rv[c][0] = rv[c][1]; rv[c][1] = rv[c][2]; rv[c][2] = rvn[c];
            }
        }
    }
}

extern "C" void kernel_launch(void* const* d_in, const int* in_sizes, int n_in,
                              void* d_out, int out_size)
{
    const float* img = (const float*)d_in[0];   // [1,3,1024,1024]
    const float* ker = (const float*)d_in[1];   // [9,1024,1024]
    float* out = (float*)d_out;                 // [1,3,1024,1024]

    // 2 width-halves x 256 row-groups = 512 CTAs of 128 threads.
    reblur_kernel<<<512, 128>>>(img, ker, out);
}